// round 3
// baseline (speedup 1.0000x reference)
#include <cuda_runtime.h>
#include <cstdint>

#define T_SEQ 128
#define E_DIM 256
#define H_DIM 64

// ---- shared memory layout (float offsets) ----
// sQ/sK/sV: [128][72]  (ld=72 => fragment bank index = gid*8+tig, conflict-free)
#define LDQ   72
#define SQ_OFF 0
#define SK_OFF (128 * 72)
#define SV_OFF (2 * 128 * 72)
#define RB_OFF (3 * 128 * 72)          // 27648: region B (phase1 staging / phase2 P)
#define SX_OFF RB_OFF                  // x chunk [128][72]
#define SW_OFF (RB_OFF + 128 * 72)     // W chunk [64][200]  (Q|K|V side by side)
#define LDW   200
#define SP_OFF RB_OFF                  // P [128][136]
#define LDP   136
#define SMEM_FLOATS (RB_OFF + 128 * 72 + 64 * 200)   // 49664 floats = 198656 B

// round fp32 -> tf32 (round-to-nearest), result kept in fp32 bit pattern
__device__ __forceinline__ float to_tf32(float x) {
    uint32_t r;
    asm volatile("cvt.rna.tf32.f32 %0, %1;" : "=r"(r) : "f"(x));
    return __uint_as_float(r);
}

__device__ __forceinline__ void mma_tf32(float* d,
                                         uint32_t a0, uint32_t a1, uint32_t a2, uint32_t a3,
                                         uint32_t b0, uint32_t b1) {
    asm volatile(
        "mma.sync.aligned.m16n8k8.row.col.f32.tf32.tf32.f32 "
        "{%0,%1,%2,%3}, {%4,%5,%6,%7}, {%8,%9}, {%0,%1,%2,%3};\n"
        : "+f"(d[0]), "+f"(d[1]), "+f"(d[2]), "+f"(d[3])
        : "r"(a0), "r"(a1), "r"(a2), "r"(a3), "r"(b0), "r"(b1));
}

__global__ __launch_bounds__(256, 1)
void attn_head_kernel(const float* __restrict__ x,
                      const float* __restrict__ Wq,
                      const float* __restrict__ Wk,
                      const float* __restrict__ Wv,
                      float* __restrict__ out) {
    extern __shared__ float smem[];

    const int tid  = threadIdx.x;
    const int warp = tid >> 5;
    const int lane = tid & 31;
    const int gid  = lane >> 2;   // groupID   (0..7)
    const int tig  = lane & 3;    // threadID_in_group (0..3)
    const size_t b = blockIdx.x;

    const float* xb = x + b * (size_t)(T_SEQ * E_DIM);
    const int r0 = warp * 16 + gid;          // this thread's "low" row

    // ---------------- Phase 1: QKV = x @ [Wq|Wk|Wv]  (tf32 MMA) ----------------
    float acc[24][4];   // 24 n-tiles of 8: n 0..63=Q, 64..127=K, 128..191=V
#pragma unroll
    for (int i = 0; i < 24; i++)
#pragma unroll
        for (int j = 0; j < 4; j++) acc[i][j] = 0.f;

    const float* Ws[3] = {Wq, Wk, Wv};

    for (int ec = 0; ec < 4; ec++) {          // E in chunks of 64
        // stage x[:, ec*64 : ec*64+64] -> sX [128][72], tf32-rounded
#pragma unroll
        for (int i = 0; i < 8; i++) {
            int q   = tid + i * 256;          // 0..2047 float4s
            int row = q >> 4;                 // 16 float4 per row
            int c4  = q & 15;
            float4 v = *reinterpret_cast<const float4*>(xb + row * E_DIM + ec * 64 + c4 * 4);
            float4 t;
            t.x = to_tf32(v.x); t.y = to_tf32(v.y); t.z = to_tf32(v.z); t.w = to_tf32(v.w);
            *reinterpret_cast<float4*>(&smem[SX_OFF + row * LDQ + c4 * 4]) = t;
        }
        // stage W{q,k,v}[ec*64 : ec*64+64, :] -> sW [64][200]
#pragma unroll
        for (int m = 0; m < 3; m++) {
            const float* Wm = Ws[m];
#pragma unroll
            for (int i = 0; i < 4; i++) {
                int q   = tid + i * 256;      // 0..1023 float4s
                int row = q >> 4;             // 0..63
                int c4  = q & 15;
                float4 v = *reinterpret_cast<const float4*>(Wm + (ec * 64 + row) * H_DIM + c4 * 4);
                float4 t;
                t.x = to_tf32(v.x); t.y = to_tf32(v.y); t.z = to_tf32(v.z); t.w = to_tf32(v.w);
                *reinterpret_cast<float4*>(&smem[SW_OFF + row * LDW + m * 64 + c4 * 4]) = t;
            }
        }
        __syncthreads();

#pragma unroll
        for (int k8 = 0; k8 < 8; k8++) {
            int kb = k8 * 8;
            uint32_t a0 = __float_as_uint(smem[SX_OFF + r0 * LDQ + kb + tig]);
            uint32_t a1 = __float_as_uint(smem[SX_OFF + (r0 + 8) * LDQ + kb + tig]);
            uint32_t a2 = __float_as_uint(smem[SX_OFF + r0 * LDQ + kb + tig + 4]);
            uint32_t a3 = __float_as_uint(smem[SX_OFF + (r0 + 8) * LDQ + kb + tig + 4]);
#pragma unroll
            for (int nt = 0; nt < 24; nt++) {
                int nb = nt * 8;
                uint32_t b0 = __float_as_uint(smem[SW_OFF + (kb + tig) * LDW + nb + gid]);
                uint32_t b1 = __float_as_uint(smem[SW_OFF + (kb + tig + 4) * LDW + nb + gid]);
                mma_tf32(acc[nt], a0, a1, a2, a3, b0, b1);
            }
        }
        __syncthreads();   // before next chunk overwrites sX/sW
    }

    // store Q, K, V (tf32-rounded) to their SMEM tiles
#pragma unroll
    for (int nt = 0; nt < 24; nt++) {
        int m  = nt >> 3;
        int nb = (nt & 7) * 8;
        int base = (m == 0) ? SQ_OFF : (m == 1) ? SK_OFF : SV_OFF;
        smem[base + r0 * LDQ + nb + tig * 2]           = to_tf32(acc[nt][0]);
        smem[base + r0 * LDQ + nb + tig * 2 + 1]       = to_tf32(acc[nt][1]);
        smem[base + (r0 + 8) * LDQ + nb + tig * 2]     = to_tf32(acc[nt][2]);
        smem[base + (r0 + 8) * LDQ + nb + tig * 2 + 1] = to_tf32(acc[nt][3]);
    }
    __syncthreads();

    // ---------------- Phase 2a: S = Q @ K^T * 0.125, causal mask, softmax ----------------
    float s[16][4];
#pragma unroll
    for (int i = 0; i < 16; i++)
#pragma unroll
        for (int j = 0; j < 4; j++) s[i][j] = 0.f;

#pragma unroll
    for (int k8 = 0; k8 < 8; k8++) {          // over H=64
        int kb = k8 * 8;
        uint32_t a0 = __float_as_uint(smem[SQ_OFF + r0 * LDQ + kb + tig]);
        uint32_t a1 = __float_as_uint(smem[SQ_OFF + (r0 + 8) * LDQ + kb + tig]);
        uint32_t a2 = __float_as_uint(smem[SQ_OFF + r0 * LDQ + kb + tig + 4]);
        uint32_t a3 = __float_as_uint(smem[SQ_OFF + (r0 + 8) * LDQ + kb + tig + 4]);
#pragma unroll
        for (int nt = 0; nt < 16; nt++) {
            int nb = nt * 8;
            uint32_t b0 = __float_as_uint(smem[SK_OFF + (nb + gid) * LDQ + kb + tig]);
            uint32_t b1 = __float_as_uint(smem[SK_OFF + (nb + gid) * LDQ + kb + tig + 4]);
            mma_tf32(s[nt], a0, a1, a2, a3, b0, b1);
        }
    }

    const float scale = 0.125f;   // 1/sqrt(64)
#pragma unroll
    for (int nt = 0; nt < 16; nt++) {
        int c0 = nt * 8 + tig * 2;
        int c1 = c0 + 1;
        s[nt][0] = (c0 <= r0)     ? s[nt][0] * scale : -1e30f;
        s[nt][1] = (c1 <= r0)     ? s[nt][1] * scale : -1e30f;
        s[nt][2] = (c0 <= r0 + 8) ? s[nt][2] * scale : -1e30f;
        s[nt][3] = (c1 <= r0 + 8) ? s[nt][3] * scale : -1e30f;
    }

    // row max (rows r0 -> regs 0,1 ; r0+8 -> regs 2,3), reduce across the 4-lane group
    float mx0 = -1e30f, mx1 = -1e30f;
#pragma unroll
    for (int nt = 0; nt < 16; nt++) {
        mx0 = fmaxf(mx0, fmaxf(s[nt][0], s[nt][1]));
        mx1 = fmaxf(mx1, fmaxf(s[nt][2], s[nt][3]));
    }
    mx0 = fmaxf(mx0, __shfl_xor_sync(0xffffffffu, mx0, 1));
    mx0 = fmaxf(mx0, __shfl_xor_sync(0xffffffffu, mx0, 2));
    mx1 = fmaxf(mx1, __shfl_xor_sync(0xffffffffu, mx1, 1));
    mx1 = fmaxf(mx1, __shfl_xor_sync(0xffffffffu, mx1, 2));

    float sm0 = 0.f, sm1 = 0.f;
#pragma unroll
    for (int nt = 0; nt < 16; nt++) {
        s[nt][0] = __expf(s[nt][0] - mx0);
        s[nt][1] = __expf(s[nt][1] - mx0);
        s[nt][2] = __expf(s[nt][2] - mx1);
        s[nt][3] = __expf(s[nt][3] - mx1);
        sm0 += s[nt][0] + s[nt][1];
        sm1 += s[nt][2] + s[nt][3];
    }
    sm0 += __shfl_xor_sync(0xffffffffu, sm0, 1);
    sm0 += __shfl_xor_sync(0xffffffffu, sm0, 2);
    sm1 += __shfl_xor_sync(0xffffffffu, sm1, 1);
    sm1 += __shfl_xor_sync(0xffffffffu, sm1, 2);
    float i0 = 1.f / sm0, i1 = 1.f / sm1;

    // store P (tf32) for re-load in A-fragment layout
#pragma unroll
    for (int nt = 0; nt < 16; nt++) {
        int c = nt * 8 + tig * 2;
        smem[SP_OFF + r0 * LDP + c]           = to_tf32(s[nt][0] * i0);
        smem[SP_OFF + r0 * LDP + c + 1]       = to_tf32(s[nt][1] * i0);
        smem[SP_OFF + (r0 + 8) * LDP + c]     = to_tf32(s[nt][2] * i1);
        smem[SP_OFF + (r0 + 8) * LDP + c + 1] = to_tf32(s[nt][3] * i1);
    }
    __syncthreads();

    // ---------------- Phase 2c: O = P @ V ----------------
    float o[8][4];
#pragma unroll
    for (int i = 0; i < 8; i++)
#pragma unroll
        for (int j = 0; j < 4; j++) o[i][j] = 0.f;

#pragma unroll
    for (int k8 = 0; k8 < 16; k8++) {         // over T=128 keys
        int kb = k8 * 8;
        uint32_t a0 = __float_as_uint(smem[SP_OFF + r0 * LDP + kb + tig]);
        uint32_t a1 = __float_as_uint(smem[SP_OFF + (r0 + 8) * LDP + kb + tig]);
        uint32_t a2 = __float_as_uint(smem[SP_OFF + r0 * LDP + kb + tig + 4]);
        uint32_t a3 = __float_as_uint(smem[SP_OFF + (r0 + 8) * LDP + kb + tig + 4]);
#pragma unroll
        for (int nt = 0; nt < 8; nt++) {
            int nb = nt * 8;
            uint32_t b0 = __float_as_uint(smem[SV_OFF + (kb + tig) * LDQ + nb + gid]);
            uint32_t b1 = __float_as_uint(smem[SV_OFF + (kb + tig + 4) * LDQ + nb + gid]);
            mma_tf32(o[nt], a0, a1, a2, a3, b0, b1);
        }
    }

    float* ob = out + b * (size_t)(T_SEQ * H_DIM);
#pragma unroll
    for (int nt = 0; nt < 8; nt++) {
        int c = nt * 8 + tig * 2;
        float2 lo = make_float2(o[nt][0], o[nt][1]);
        float2 hi = make_float2(o[nt][2], o[nt][3]);
        *reinterpret_cast<float2*>(ob + r0 * H_DIM + c)       = lo;
        *reinterpret_cast<float2*>(ob + (r0 + 8) * H_DIM + c) = hi;
    }
}

extern "C" void kernel_launch(void* const* d_in, const int* in_sizes, int n_in,
                              void* d_out, int out_size) {
    const float* x  = (const float*)d_in[0];
    const float* Wq = (const float*)d_in[1];
    const float* Wk = (const float*)d_in[2];
    const float* Wv = (const float*)d_in[3];
    float* out = (float*)d_out;

    int B = in_sizes[0] / (T_SEQ * E_DIM);   // 4096
    size_t smem_bytes = SMEM_FLOATS * sizeof(float);   // 198656

    cudaFuncSetAttribute(attn_head_kernel,
                         cudaFuncAttributeMaxDynamicSharedMemorySize,
                         (int)smem_bytes);

    attn_head_kernel<<<B, 256, smem_bytes>>>(x, Wq, Wk, Wv, out);
}

// round 7
// speedup vs baseline: 1.3551x; 1.3551x over previous
#include <cuda_runtime.h>
#include <cuda_fp16.h>
#include <cstdint>

#define T_SEQ 128
#define E_DIM 256
#define H_DIM 64

// ---- SMEM byte layout ----
#define SQ_B   0u          // Q [128][72]h
#define SK_B   18432u      // K [128][72]h
#define SV_B   36864u      // V [128][72]h  (row=token, col=h)
#define SX0_B  55296u      // x stage buf0 [128][72]h
#define SX1_B  73728u      // x stage buf1
#define SW0_B  92160u      // W stage buf0 [192][72]h
#define SW1_B  119808u     // W stage buf1
#define SP_B   55296u      // P [128][136]h (reuses x stages)
#define PM_B   147456u     // float[4][128] partial row max
#define PS_B   149504u     // float[4][128] partial row sum
#define SMEM_BYTES 151552u

#define LDA 144            // 72 halves per row
#define LDPB 272           // 136 halves per row

// W pre-converted fp16, pre-transposed: [ec(4)][n(192)=Wq|Wk|Wv rows][k(72)]
__device__ __align__(16) __half g_wt[4 * 192 * 72];

// ---------------- helpers ----------------
__device__ __forceinline__ uint32_t smem_u32(const void* p) {
    uint32_t a;
    asm("{ .reg .u64 t; cvta.to.shared.u64 t, %1; cvt.u32.u64 %0, t; }" : "=r"(a) : "l"(p));
    return a;
}
__device__ __forceinline__ uint32_t pack2(float lo, float hi) {
    uint32_t r;
    asm("cvt.rn.f16x2.f32 %0, %1, %2;" : "=r"(r) : "f"(hi), "f"(lo));  // first src -> high
    return r;
}
#define LDSM_X4(R, a) \
    asm volatile("ldmatrix.sync.aligned.m8n8.x4.shared.b16 {%0,%1,%2,%3}, [%4];" \
        : "=r"((R)[0]), "=r"((R)[1]), "=r"((R)[2]), "=r"((R)[3]) : "r"(a))
#define LDSM_X4T(R, a) \
    asm volatile("ldmatrix.sync.aligned.m8n8.x4.trans.shared.b16 {%0,%1,%2,%3}, [%4];" \
        : "=r"((R)[0]), "=r"((R)[1]), "=r"((R)[2]), "=r"((R)[3]) : "r"(a))
#define MMA16816(D, A, B0, B1) \
    asm volatile("mma.sync.aligned.m16n8k16.row.col.f32.f16.f16.f32 " \
        "{%0,%1,%2,%3}, {%4,%5,%6,%7}, {%8,%9}, {%0,%1,%2,%3};" \
        : "+f"((D)[0]), "+f"((D)[1]), "+f"((D)[2]), "+f"((D)[3]) \
        : "r"((A)[0]), "r"((A)[1]), "r"((A)[2]), "r"((A)[3]), "r"(B0), "r"(B1))
#define CP_ASYNC16(dst, src) \
    asm volatile("cp.async.cg.shared.global [%0], [%1], 16;" :: "r"(dst), "l"(src))
#define CP_COMMIT()  asm volatile("cp.async.commit_group;" ::: "memory")
#define CP_WAIT0()   asm volatile("cp.async.wait_group 0;" ::: "memory")

// ---------------- W prep: fp32 [E][H] -> fp16 tiles [ec][n][72] ----------------
__global__ void prep_w_kernel(const float* __restrict__ Wq,
                              const float* __restrict__ Wk,
                              const float* __restrict__ Wv) {
    int blk = blockIdx.x;             // ec*3 + m
    int ec = blk / 3, m = blk % 3;
    const float* W = (m == 0) ? Wq : (m == 1) ? Wk : Wv;
#pragma unroll
    for (int i = 0; i < 16; i++) {
        int e = threadIdx.x + i * 256;      // 0..4095
        int h = e >> 6, k = e & 63;
        g_wt[((size_t)ec * 192 + m * 64 + h) * 72 + k] =
            __float2half_rn(W[(ec * 64 + k) * H_DIM + h]);
    }
}

// ---------------- main kernel ----------------
__global__ __launch_bounds__(256)
void attn_fp16_kernel(const float* __restrict__ x, float* __restrict__ out) {
    extern __shared__ char smem[];
    const uint32_t sbase = smem_u32(smem);
    const int tid = threadIdx.x, warp = tid >> 5, lane = tid & 31;
    const int g = lane >> 2, t = lane & 3;
    const int wm = warp & 1, wn = warp >> 1;     // 2 x 4 warp grid
    const int m0 = wm * 64;
    const size_t b = blockIdx.x;
    const float* xb = x + b * (size_t)(T_SEQ * E_DIM);

    // =============== Phase 1: QKV = x @ Wt  (E chunked x4, pipelined) ===============
    float acc1[4][6][4];
#pragma unroll
    for (int i = 0; i < 4; i++)
#pragma unroll
        for (int j = 0; j < 6; j++)
#pragma unroll
            for (int r = 0; r < 4; r++) acc1[i][j][r] = 0.f;

    const int n01 = wn * 48;
    float4 xr[8];

    // prologue: stage chunk 0
    {
#pragma unroll
        for (int i = 0; i < 4; i++) {
            int q = tid + i * 256, r = q >> 3, c8 = q & 7;
            const float* p = xb + r * E_DIM + c8 * 8;
            xr[2 * i]     = *reinterpret_cast<const float4*>(p);
            xr[2 * i + 1] = *reinterpret_cast<const float4*>(p + 4);
        }
        const char* wsrc = reinterpret_cast<const char*>(g_wt);
#pragma unroll
        for (int i = 0; i < 7; i++) {
            int idx = tid + i * 256;
            if (idx < 1728) CP_ASYNC16(sbase + SW0_B + idx * 16, wsrc + idx * 16);
        }
        CP_COMMIT();
#pragma unroll
        for (int i = 0; i < 4; i++) {
            int q = tid + i * 256, r = q >> 3, c8 = q & 7;
            uint4 u;
            u.x = pack2(xr[2 * i].x,     xr[2 * i].y);
            u.y = pack2(xr[2 * i].z,     xr[2 * i].w);
            u.z = pack2(xr[2 * i + 1].x, xr[2 * i + 1].y);
            u.w = pack2(xr[2 * i + 1].z, xr[2 * i + 1].w);
            *reinterpret_cast<uint4*>(smem + SX0_B + r * LDA + c8 * 16) = u;
        }
        CP_WAIT0();
        __syncthreads();
    }

#pragma unroll
    for (int ec = 0; ec < 4; ec++) {
        const uint32_t sx = sbase + ((ec & 1) ? SX1_B : SX0_B);
        const uint32_t sw = sbase + ((ec & 1) ? SW1_B : SW0_B);
        const uint32_t sxn = sbase + ((ec & 1) ? SX0_B : SX1_B);
        const uint32_t swn = sbase + ((ec & 1) ? SW0_B : SW1_B);

        if (ec < 3) {   // prefetch next chunk: x -> regs, W -> cp.async
#pragma unroll
            for (int i = 0; i < 4; i++) {
                int q = tid + i * 256, r = q >> 3, c8 = q & 7;
                const float* p = xb + r * E_DIM + (ec + 1) * 64 + c8 * 8;
                xr[2 * i]     = *reinterpret_cast<const float4*>(p);
                xr[2 * i + 1] = *reinterpret_cast<const float4*>(p + 4);
            }
            const char* wsrc = reinterpret_cast<const char*>(g_wt) + (size_t)(ec + 1) * 27648;
#pragma unroll
            for (int i = 0; i < 7; i++) {
                int idx = tid + i * 256;
                if (idx < 1728) CP_ASYNC16(swn + idx * 16, wsrc + idx * 16);
            }
            CP_COMMIT();
        }

        // MMA over this chunk (K=64 -> 4 k16 steps)
        const uint32_t arow = sx + (m0 + (lane & 15)) * LDA + (lane >> 4) * 16;
        const uint32_t brow = sw + (n01 + ((lane >> 4) << 3) + (lane & 7)) * LDA
                                 + ((lane >> 3) & 1) * 16;
#pragma unroll
        for (int kt = 0; kt < 4; kt++) {
            uint32_t a[4][4], bf[3][4];
#pragma unroll
            for (int mt = 0; mt < 4; mt++) LDSM_X4(a[mt], arow + mt * 16 * LDA + kt * 32);
#pragma unroll
            for (int bt = 0; bt < 3; bt++) LDSM_X4(bf[bt], brow + bt * 16 * LDA + kt * 32);
#pragma unroll
            for (int mt = 0; mt < 4; mt++)
#pragma unroll
                for (int nt = 0; nt < 6; nt++)
                    MMA16816(acc1[mt][nt], a[mt], bf[nt >> 1][(nt & 1) * 2],
                             bf[nt >> 1][(nt & 1) * 2 + 1]);
        }

        if (ec < 3) {   // store prefetched x into the other buffer
#pragma unroll
            for (int i = 0; i < 4; i++) {
                int q = tid + i * 256, r = q >> 3, c8 = q & 7;
                uint4 u;
                u.x = pack2(xr[2 * i].x,     xr[2 * i].y);
                u.y = pack2(xr[2 * i].z,     xr[2 * i].w);
                u.z = pack2(xr[2 * i + 1].x, xr[2 * i + 1].y);
                u.w = pack2(xr[2 * i + 1].z, xr[2 * i + 1].w);
                *reinterpret_cast<uint4*>((char*)smem + (sxn - sbase) + r * LDA + c8 * 16) = u;
            }
        }
        CP_WAIT0();
        __syncthreads();
    }

    // epilogue 1: acc -> fp16 Q/K/V tiles
#pragma unroll
    for (int mt = 0; mt < 4; mt++) {
        int rlo = m0 + mt * 16 + g, rhi = rlo + 8;
#pragma unroll
        for (int nt = 0; nt < 6; nt++) {
            int cg = n01 + nt * 8 + t * 2;
            int sel = cg >> 6, cl = cg & 63;
            uint32_t base = (sel == 0) ? SQ_B : (sel == 1) ? SK_B : SV_B;
            *reinterpret_cast<uint32_t*>(smem + base + rlo * LDA + cl * 2) =
                pack2(acc1[mt][nt][0], acc1[mt][nt][1]);
            *reinterpret_cast<uint32_t*>(smem + base + rhi * LDA + cl * 2) =
                pack2(acc1[mt][nt][2], acc1[mt][nt][3]);
        }
    }
    __syncthreads();

    // =============== Phase 2a: S = Q @ K^T, causal softmax -> P ===============
    const int n02 = wn * 32;
    const bool active = (n02 <= m0 + 63);
    float acc2[4][4][4];
    float* pm = reinterpret_cast<float*>(smem + PM_B);
    float* ps = reinterpret_cast<float*>(smem + PS_B);
    float fscale[4][2];   // per (mt, lo/hi) final multipliers

    if (active) {
#pragma unroll
        for (int i = 0; i < 4; i++)
#pragma unroll
            for (int j = 0; j < 4; j++)
#pragma unroll
                for (int r = 0; r < 4; r++) acc2[i][j][r] = 0.f;

        const uint32_t arow = sbase + SQ_B + (m0 + (lane & 15)) * LDA + (lane >> 4) * 16;
        const uint32_t brow = sbase + SK_B + (n02 + ((lane >> 4) << 3) + (lane & 7)) * LDA
                                          + ((lane >> 3) & 1) * 16;
#pragma unroll
        for (int kt = 0; kt < 4; kt++) {
            uint32_t a[4][4], bf[2][4];
#pragma unroll
            for (int mt = 0; mt < 4; mt++) LDSM_X4(a[mt], arow + mt * 16 * LDA + kt * 32);
#pragma unroll
            for (int bt = 0; bt < 2; bt++) LDSM_X4(bf[bt], brow + bt * 16 * LDA + kt * 32);
#pragma unroll
            for (int mt = 0; mt < 4; mt++)
#pragma unroll
                for (int nt = 0; nt < 4; nt++)
                    MMA16816(acc2[mt][nt], a[mt], bf[nt >> 1][(nt & 1) * 2],
                             bf[nt >> 1][(nt & 1) * 2 + 1]);
        }

        // mask + local (32-col chunk) softmax partials
#pragma unroll
        for (int mt = 0; mt < 4; mt++) {
            int rlo = m0 + mt * 16 + g, rhi = rlo + 8;
            float mlo = -1e30f, mhi = -1e30f;
#pragma unroll
            for (int nt = 0; nt < 4; nt++)
#pragma unroll
                for (int j = 0; j < 2; j++) {
                    int c = n02 + nt * 8 + t * 2 + j;
                    float v0 = acc2[mt][nt][j] * 0.125f;
                    v0 = (c <= rlo) ? v0 : -1e30f;
                    acc2[mt][nt][j] = v0; mlo = fmaxf(mlo, v0);
                    float v1 = acc2[mt][nt][2 + j] * 0.125f;
                    v1 = (c <= rhi) ? v1 : -1e30f;
                    acc2[mt][nt][2 + j] = v1; mhi = fmaxf(mhi, v1);
                }
            mlo = fmaxf(mlo, __shfl_xor_sync(0xffffffffu, mlo, 1));
            mlo = fmaxf(mlo, __shfl_xor_sync(0xffffffffu, mlo, 2));
            mhi = fmaxf(mhi, __shfl_xor_sync(0xffffffffu, mhi, 1));
            mhi = fmaxf(mhi, __shfl_xor_sync(0xffffffffu, mhi, 2));
            float slo = 0.f, shi = 0.f;
#pragma unroll
            for (int nt = 0; nt < 4; nt++)
#pragma unroll
                for (int j = 0; j < 2; j++) {
                    float e0 = __expf(acc2[mt][nt][j] - mlo);
                    float e1 = __expf(acc2[mt][nt][2 + j] - mhi);
                    acc2[mt][nt][j] = e0;  acc2[mt][nt][2 + j] = e1;
                    slo += e0; shi += e1;
                }
            slo += __shfl_xor_sync(0xffffffffu, slo, 1);
            slo += __shfl_xor_sync(0xffffffffu, slo, 2);
            shi += __shfl_xor_sync(0xffffffffu, shi, 1);
            shi += __shfl_xor_sync(0xffffffffu, shi, 2);
            if (t == 0) {
                pm[wn * 128 + rlo] = mlo;  pm[wn * 128 + rhi] = mhi;
                ps[wn * 128 + rlo] = slo;  ps[wn * 128 + rhi] = shi;
            }
            fscale[mt][0] = mlo;  fscale[mt][1] = mhi;   // stash local max
        }
    } else {
        // fully masked tile: contribute nothing
        if (t == 0) {
#pragma unroll
            for (int mt = 0; mt < 4; mt++) {
                int rlo = m0 + mt * 16 + g, rhi = rlo + 8;
                pm[wn * 128 + rlo] = -1e30f;  pm[wn * 128 + rhi] = -1e30f;
                ps[wn * 128 + rlo] = 0.f;     ps[wn * 128 + rhi] = 0.f;
            }
        }
    }
    __syncthreads();

    // combine partials, write P (fp16)
#pragma unroll
    for (int mt = 0; mt < 4; mt++) {
        int rlo = m0 + mt * 16 + g, rhi = rlo + 8;
        if (active) {
            float M0 = pm[rlo], M1 = pm[128 + rlo], M2 = pm[256 + rlo], M3 = pm[384 + rlo];
            float Mlo = fmaxf(fmaxf(M0, M1), fmaxf(M2, M3));
            float Zlo = ps[rlo] * __expf(M0 - Mlo) + ps[128 + rlo] * __expf(M1 - Mlo)
                      + ps[256 + rlo] * __expf(M2 - Mlo) + ps[384 + rlo] * __expf(M3 - Mlo);
            float N0 = pm[rhi], N1 = pm[128 + rhi], N2 = pm[256 + rhi], N3 = pm[384 + rhi];
            float Mhi = fmaxf(fmaxf(N0, N1), fmaxf(N2, N3));
            float Zhi = ps[rhi] * __expf(N0 - Mhi) + ps[128 + rhi] * __expf(N1 - Mhi)
                      + ps[256 + rhi] * __expf(N2 - Mhi) + ps[384 + rhi] * __expf(N3 - Mhi);
            float flo = __expf(fscale[mt][0] - Mlo) / Zlo;
            float fhi = __expf(fscale[mt][1] - Mhi) / Zhi;
#pragma unroll
            for (int nt = 0; nt < 4; nt++) {
                int c = n02 + nt * 8 + t * 2;
                *reinterpret_cast<uint32_t*>(smem + SP_B + rlo * LDPB + c * 2) =
                    pack2(acc2[mt][nt][0] * flo, acc2[mt][nt][1] * flo);
                *reinterpret_cast<uint32_t*>(smem + SP_B + rhi * LDPB + c * 2) =
                    pack2(acc2[mt][nt][2] * fhi, acc2[mt][nt][3] * fhi);
            }
        } else {
#pragma unroll
            for (int nt = 0; nt < 4; nt++) {
                int c = n02 + nt * 8 + t * 2;
                *reinterpret_cast<uint32_t*>(smem + SP_B + rlo * LDPB + c * 2) = 0u;
                *reinterpret_cast<uint32_t*>(smem + SP_B + rhi * LDPB + c * 2) = 0u;
            }
        }
    }
    __syncthreads();

    // =============== Phase 2c: O = P @ V ===============
    const int n03 = wn * 16;
    float acc3[4][2][4];
#pragma unroll
    for (int i = 0; i < 4; i++)
#pragma unroll
        for (int j = 0; j < 2; j++)
#pragma unroll
            for (int r = 0; r < 4; r++) acc3[i][j][r] = 0.f;

    const uint32_t prow = sbase + SP_B + (m0 + (lane & 15)) * LDPB + (lane >> 4) * 16;
#pragma unroll
    for (int kt = 0; kt < 8; kt++) {
        uint32_t a[4][4], bv[4];
#pragma unroll
        for (int mt = 0; mt < 4; mt++) LDSM_X4(a[mt], prow + mt * 16 * LDPB + kt * 32);
        uint32_t vaddr = sbase + SV_B
                       + (kt * 16 + ((lane >> 3) & 1) * 8 + (lane & 7)) * LDA
                       + (lane >> 4) * 16 + n03 * 2;
        LDSM_X4T(bv, vaddr);
#pragma unroll
        for (int mt = 0; mt < 4; mt++) {
            MMA16816(acc3[mt][0], a[mt], bv[0], bv[1]);
            MMA16816(acc3[mt][1], a[mt], bv[2], bv[3]);
        }
    }

    // output: fp32 float2 stores
    float* ob = out + b * (size_t)(T_SEQ * H_DIM);
#pragma unroll
    for (int mt = 0; mt < 4; mt++) {
        int rlo = m0 + mt * 16 + g, rhi = rlo + 8;
#pragma unroll
        for (int nt = 0; nt < 2; nt++) {
            int c = n03 + nt * 8 + t * 2;
            *reinterpret_cast<float2*>(ob + rlo * H_DIM + c) =
                make_float2(acc3[mt][nt][0], acc3[mt][nt][1]);
            *reinterpret_cast<float2*>(ob + rhi * H_DIM + c) =
                make_float2(acc3[mt][nt][2], acc3[mt][nt][3]);
        }
    }
}

extern "C" void kernel_launch(void* const* d_in, const int* in_sizes, int n_in,
                              void* d_out, int out_size) {
    const float* x  = (const float*)d_in[0];
    const float* Wq = (const float*)d_in[1];
    const float* Wk = (const float*)d_in[2];
    const float* Wv = (const float*)d_in[3];
    float* out = (float*)d_out;

    int B = in_sizes[0] / (T_SEQ * E_DIM);   // 4096

    cudaFuncSetAttribute(attn_fp16_kernel,
                         cudaFuncAttributeMaxDynamicSharedMemorySize,
                         (int)SMEM_BYTES);

    prep_w_kernel<<<12, 256>>>(Wq, Wk, Wv);
    attn_fp16_kernel<<<B, 256, SMEM_BYTES>>>(x, out);
}

// round 9
// speedup vs baseline: 2.0942x; 1.5455x over previous
#include <cuda_runtime.h>
#include <cuda_fp16.h>
#include <cstdint>

#define T_SEQ 128
#define E_DIM 256
#define H_DIM 64

// ---- SMEM byte layout ----
#define SQ_B   0u          // Q [128][72]h
#define SK_B   18432u      // K [128][72]h
#define SV_B   36864u      // V [128][72]h  (row=token, col=h)
#define SX0_B  55296u      // x stage buf0 [128][72]h
#define SX1_B  73728u      // x stage buf1
#define SW0_B  92160u      // W stage buf0 [192][72]h
#define SW1_B  119808u     // W stage buf1
#define SP_B   55296u      // P [128][136]h (reuses x stages)
#define PM_B   147456u     // float[4][128] partial row max
#define PS_B   149504u     // float[4][128] partial row sum
#define SMEM_BYTES 151552u

#define LDA 144            // 72 halves per row
#define LDPB 272           // 136 halves per row

// W pre-converted fp16, pre-transposed: [ec(4)][n(192)=Wq|Wk|Wv rows][k(72)]
__device__ __align__(16) __half g_wt[4 * 192 * 72];

// ---------------- helpers ----------------
__device__ __forceinline__ uint32_t smem_u32(const void* p) {
    uint32_t a;
    asm("{ .reg .u64 t; cvta.to.shared.u64 t, %1; cvt.u32.u64 %0, t; }" : "=r"(a) : "l"(p));
    return a;
}
__device__ __forceinline__ uint32_t pack2(float lo, float hi) {
    uint32_t r;
    asm("cvt.rn.f16x2.f32 %0, %1, %2;" : "=r"(r) : "f"(hi), "f"(lo));  // first src -> high
    return r;
}
#define LDSM_X4(R, a) \
    asm volatile("ldmatrix.sync.aligned.m8n8.x4.shared.b16 {%0,%1,%2,%3}, [%4];" \
        : "=r"((R)[0]), "=r"((R)[1]), "=r"((R)[2]), "=r"((R)[3]) : "r"(a))
#define LDSM_X4T(R, a) \
    asm volatile("ldmatrix.sync.aligned.m8n8.x4.trans.shared.b16 {%0,%1,%2,%3}, [%4];" \
        : "=r"((R)[0]), "=r"((R)[1]), "=r"((R)[2]), "=r"((R)[3]) : "r"(a))
#define MMA16816(D, A, B0, B1) \
    asm volatile("mma.sync.aligned.m16n8k16.row.col.f32.f16.f16.f32 " \
        "{%0,%1,%2,%3}, {%4,%5,%6,%7}, {%8,%9}, {%0,%1,%2,%3};" \
        : "+f"((D)[0]), "+f"((D)[1]), "+f"((D)[2]), "+f"((D)[3]) \
        : "r"((A)[0]), "r"((A)[1]), "r"((A)[2]), "r"((A)[3]), "r"(B0), "r"(B1))
#define CP_ASYNC16(dst, src) \
    asm volatile("cp.async.cg.shared.global [%0], [%1], 16;" :: "r"(dst), "l"(src))
#define CP_COMMIT()  asm volatile("cp.async.commit_group;" ::: "memory")
#define CP_WAIT0()   asm volatile("cp.async.wait_group 0;" ::: "memory")

// ---------------- W prep: fp32 [E][H] -> fp16 tiles [ec][n][72] ----------------
__global__ void prep_w_kernel(const float* __restrict__ Wq,
                              const float* __restrict__ Wk,
                              const float* __restrict__ Wv) {
    int blk = blockIdx.x;             // ec*3 + m
    int ec = blk / 3, m = blk % 3;
    const float* W = (m == 0) ? Wq : (m == 1) ? Wk : Wv;
#pragma unroll
    for (int i = 0; i < 16; i++) {
        int e = threadIdx.x + i * 256;      // 0..4095
        int h = e >> 6, k = e & 63;
        g_wt[((size_t)ec * 192 + m * 64 + h) * 72 + k] =
            __float2half_rn(W[(ec * 64 + k) * H_DIM + h]);
    }
}

// ---------------- main kernel: 512 threads, 16 warps ----------------
__global__ __launch_bounds__(512, 1)
void attn_fp16_kernel(const float* __restrict__ x, float* __restrict__ out) {
    extern __shared__ char smem[];
    const uint32_t sbase = smem_u32(smem);
    const int tid = threadIdx.x, warp = tid >> 5, lane = tid & 31;
    const int g = lane >> 2, t = lane & 3;
    const int wm = warp & 3, wn = warp >> 2;     // 4 x 4 warp grid
    const int m0 = wm * 32;
    const size_t b = blockIdx.x;
    const float* xb = x + b * (size_t)(T_SEQ * E_DIM);

    // =============== Phase 1: QKV = x @ Wt  (E chunked x4, pipelined) ===============
    float acc1[2][6][4];
#pragma unroll
    for (int i = 0; i < 2; i++)
#pragma unroll
        for (int j = 0; j < 6; j++)
#pragma unroll
            for (int r = 0; r < 4; r++) acc1[i][j][r] = 0.f;

    const int n01 = wn * 48;
    float4 xr[4];

    // prologue: stage chunk 0
    {
#pragma unroll
        for (int i = 0; i < 2; i++) {
            int q = tid + i * 512, r = q >> 3, c8 = q & 7;
            const float* p = xb + r * E_DIM + c8 * 8;
            xr[2 * i]     = *reinterpret_cast<const float4*>(p);
            xr[2 * i + 1] = *reinterpret_cast<const float4*>(p + 4);
        }
        const char* wsrc = reinterpret_cast<const char*>(g_wt);
#pragma unroll
        for (int i = 0; i < 4; i++) {
            int idx = tid + i * 512;
            if (idx < 1728) CP_ASYNC16(sbase + SW0_B + idx * 16, wsrc + idx * 16);
        }
        CP_COMMIT();
#pragma unroll
        for (int i = 0; i < 2; i++) {
            int q = tid + i * 512, r = q >> 3, c8 = q & 7;
            uint4 u;
            u.x = pack2(xr[2 * i].x,     xr[2 * i].y);
            u.y = pack2(xr[2 * i].z,     xr[2 * i].w);
            u.z = pack2(xr[2 * i + 1].x, xr[2 * i + 1].y);
            u.w = pack2(xr[2 * i + 1].z, xr[2 * i + 1].w);
            *reinterpret_cast<uint4*>(smem + SX0_B + r * LDA + c8 * 16) = u;
        }
        CP_WAIT0();
        __syncthreads();
    }

#pragma unroll
    for (int ec = 0; ec < 4; ec++) {
        const uint32_t sx = sbase + ((ec & 1) ? SX1_B : SX0_B);
        const uint32_t sw = sbase + ((ec & 1) ? SW1_B : SW0_B);
        const uint32_t sxn = sbase + ((ec & 1) ? SX0_B : SX1_B);
        const uint32_t swn = sbase + ((ec & 1) ? SW0_B : SW1_B);

        if (ec < 3) {   // prefetch next chunk: x -> regs, W -> cp.async
#pragma unroll
            for (int i = 0; i < 2; i++) {
                int q = tid + i * 512, r = q >> 3, c8 = q & 7;
                const float* p = xb + r * E_DIM + (ec + 1) * 64 + c8 * 8;
                xr[2 * i]     = *reinterpret_cast<const float4*>(p);
                xr[2 * i + 1] = *reinterpret_cast<const float4*>(p + 4);
            }
            const char* wsrc = reinterpret_cast<const char*>(g_wt) + (size_t)(ec + 1) * 27648;
#pragma unroll
            for (int i = 0; i < 4; i++) {
                int idx = tid + i * 512;
                if (idx < 1728) CP_ASYNC16(swn + idx * 16, wsrc + idx * 16);
            }
            CP_COMMIT();
        }

        // MMA over this chunk (K=64 -> 4 k16 steps)
        const uint32_t arow = sx + (m0 + (lane & 15)) * LDA + (lane >> 4) * 16;
        const uint32_t brow = sw + (n01 + ((lane >> 4) << 3) + (lane & 7)) * LDA
                                 + ((lane >> 3) & 1) * 16;
#pragma unroll
        for (int kt = 0; kt < 4; kt++) {
            uint32_t a[2][4], bf[3][4];
#pragma unroll
            for (int mt = 0; mt < 2; mt++) LDSM_X4(a[mt], arow + mt * 16 * LDA + kt * 32);
#pragma unroll
            for (int bt = 0; bt < 3; bt++) LDSM_X4(bf[bt], brow + bt * 16 * LDA + kt * 32);
#pragma unroll
            for (int mt = 0; mt < 2; mt++)
#pragma unroll
                for (int nt = 0; nt < 6; nt++)
                    MMA16816(acc1[mt][nt], a[mt], bf[nt >> 1][(nt & 1) * 2],
                             bf[nt >> 1][(nt & 1) * 2 + 1]);
        }

        if (ec < 3) {   // store prefetched x into the other buffer
#pragma unroll
            for (int i = 0; i < 2; i++) {
                int q = tid + i * 512, r = q >> 3, c8 = q & 7;
                uint4 u;
                u.x = pack2(xr[2 * i].x,     xr[2 * i].y);
                u.y = pack2(xr[2 * i].z,     xr[2 * i].w);
                u.z = pack2(xr[2 * i + 1].x, xr[2 * i + 1].y);
                u.w = pack2(xr[2 * i + 1].z, xr[2 * i + 1].w);
                *reinterpret_cast<uint4*>((char*)smem + (sxn - sbase) + r * LDA + c8 * 16) = u;
            }
        }
        CP_WAIT0();
        __syncthreads();
    }

    // epilogue 1: acc -> fp16 Q/K/V tiles
#pragma unroll
    for (int mt = 0; mt < 2; mt++) {
        int rlo = m0 + mt * 16 + g, rhi = rlo + 8;
#pragma unroll
        for (int nt = 0; nt < 6; nt++) {
            int cg = n01 + nt * 8 + t * 2;
            int sel = cg >> 6, cl = cg & 63;
            uint32_t base = (sel == 0) ? SQ_B : (sel == 1) ? SK_B : SV_B;
            *reinterpret_cast<uint32_t*>(smem + base + rlo * LDA + cl * 2) =
                pack2(acc1[mt][nt][0], acc1[mt][nt][1]);
            *reinterpret_cast<uint32_t*>(smem + base + rhi * LDA + cl * 2) =
                pack2(acc1[mt][nt][2], acc1[mt][nt][3]);
        }
    }
    __syncthreads();

    // =============== Phase 2a: S = Q @ K^T, causal softmax -> P ===============
    const int n02 = wn * 32;
    const bool active = (n02 <= m0 + 31);     // wn <= wm
    float acc2[2][4][4];
    float* pm = reinterpret_cast<float*>(smem + PM_B);
    float* ps = reinterpret_cast<float*>(smem + PS_B);
    float fscale[2][2];   // per (mt, lo/hi) local max stash

    if (active) {
#pragma unroll
        for (int i = 0; i < 2; i++)
#pragma unroll
            for (int j = 0; j < 4; j++)
#pragma unroll
                for (int r = 0; r < 4; r++) acc2[i][j][r] = 0.f;

        const uint32_t arow = sbase + SQ_B + (m0 + (lane & 15)) * LDA + (lane >> 4) * 16;
        const uint32_t brow = sbase + SK_B + (n02 + ((lane >> 4) << 3) + (lane & 7)) * LDA
                                          + ((lane >> 3) & 1) * 16;
#pragma unroll
        for (int kt = 0; kt < 4; kt++) {
            uint32_t a[2][4], bf[2][4];
#pragma unroll
            for (int mt = 0; mt < 2; mt++) LDSM_X4(a[mt], arow + mt * 16 * LDA + kt * 32);
#pragma unroll
            for (int bt = 0; bt < 2; bt++) LDSM_X4(bf[bt], brow + bt * 16 * LDA + kt * 32);
#pragma unroll
            for (int mt = 0; mt < 2; mt++)
#pragma unroll
                for (int nt = 0; nt < 4; nt++)
                    MMA16816(acc2[mt][nt], a[mt], bf[nt >> 1][(nt & 1) * 2],
                             bf[nt >> 1][(nt & 1) * 2 + 1]);
        }

        // mask + local (32-col chunk) softmax partials
#pragma unroll
        for (int mt = 0; mt < 2; mt++) {
            int rlo = m0 + mt * 16 + g, rhi = rlo + 8;
            float mlo = -1e30f, mhi = -1e30f;
#pragma unroll
            for (int nt = 0; nt < 4; nt++)
#pragma unroll
                for (int j = 0; j < 2; j++) {
                    int c = n02 + nt * 8 + t * 2 + j;
                    float v0 = acc2[mt][nt][j] * 0.125f;
                    v0 = (c <= rlo) ? v0 : -1e30f;
                    acc2[mt][nt][j] = v0; mlo = fmaxf(mlo, v0);
                    float v1 = acc2[mt][nt][2 + j] * 0.125f;
                    v1 = (c <= rhi) ? v1 : -1e30f;
                    acc2[mt][nt][2 + j] = v1; mhi = fmaxf(mhi, v1);
                }
            mlo = fmaxf(mlo, __shfl_xor_sync(0xffffffffu, mlo, 1));
            mlo = fmaxf(mlo, __shfl_xor_sync(0xffffffffu, mlo, 2));
            mhi = fmaxf(mhi, __shfl_xor_sync(0xffffffffu, mhi, 1));
            mhi = fmaxf(mhi, __shfl_xor_sync(0xffffffffu, mhi, 2));
            float slo = 0.f, shi = 0.f;
#pragma unroll
            for (int nt = 0; nt < 4; nt++)
#pragma unroll
                for (int j = 0; j < 2; j++) {
                    float e0 = __expf(acc2[mt][nt][j] - mlo);
                    float e1 = __expf(acc2[mt][nt][2 + j] - mhi);
                    acc2[mt][nt][j] = e0;  acc2[mt][nt][2 + j] = e1;
                    slo += e0; shi += e1;
                }
            slo += __shfl_xor_sync(0xffffffffu, slo, 1);
            slo += __shfl_xor_sync(0xffffffffu, slo, 2);
            shi += __shfl_xor_sync(0xffffffffu, shi, 1);
            shi += __shfl_xor_sync(0xffffffffu, shi, 2);
            if (t == 0) {
                pm[wn * 128 + rlo] = mlo;  pm[wn * 128 + rhi] = mhi;
                ps[wn * 128 + rlo] = slo;  ps[wn * 128 + rhi] = shi;
            }
            fscale[mt][0] = mlo;  fscale[mt][1] = mhi;
        }
    } else {
        // fully masked tile: contribute nothing
        if (t == 0) {
#pragma unroll
            for (int mt = 0; mt < 2; mt++) {
                int rlo = m0 + mt * 16 + g, rhi = rlo + 8;
                pm[wn * 128 + rlo] = -1e30f;  pm[wn * 128 + rhi] = -1e30f;
                ps[wn * 128 + rlo] = 0.f;     ps[wn * 128 + rhi] = 0.f;
            }
        }
    }
    __syncthreads();

    // combine partials, write P (fp16)
#pragma unroll
    for (int mt = 0; mt < 2; mt++) {
        int rlo = m0 + mt * 16 + g, rhi = rlo + 8;
        if (active) {
            float M0 = pm[rlo], M1 = pm[128 + rlo], M2 = pm[256 + rlo], M3 = pm[384 + rlo];
            float Mlo = fmaxf(fmaxf(M0, M1), fmaxf(M2, M3));
            float Zlo = ps[rlo] * __expf(M0 - Mlo) + ps[128 + rlo] * __expf(M1 - Mlo)
                      + ps[256 + rlo] * __expf(M2 - Mlo) + ps[384 + rlo] * __expf(M3 - Mlo);
            float N0 = pm[rhi], N1 = pm[128 + rhi], N2 = pm[256 + rhi], N3 = pm[384 + rhi];
            float Mhi = fmaxf(fmaxf(N0, N1), fmaxf(N2, N3));
            float Zhi = ps[rhi] * __expf(N0 - Mhi) + ps[128 + rhi] * __expf(N1 - Mhi)
                      + ps[256 + rhi] * __expf(N2 - Mhi) + ps[384 + rhi] * __expf(N3 - Mhi);
            float flo = __expf(fscale[mt][0] - Mlo) / Zlo;
            float fhi = __expf(fscale[mt][1] - Mhi) / Zhi;
#pragma unroll
            for (int nt = 0; nt < 4; nt++) {
                int c = n02 + nt * 8 + t * 2;
                *reinterpret_cast<uint32_t*>(smem + SP_B + rlo * LDPB + c * 2) =
                    pack2(acc2[mt][nt][0] * flo, acc2[mt][nt][1] * flo);
                *reinterpret_cast<uint32_t*>(smem + SP_B + rhi * LDPB + c * 2) =
                    pack2(acc2[mt][nt][2] * fhi, acc2[mt][nt][3] * fhi);
            }
        } else {
#pragma unroll
            for (int nt = 0; nt < 4; nt++) {
                int c = n02 + nt * 8 + t * 2;
                *reinterpret_cast<uint32_t*>(smem + SP_B + rlo * LDPB + c * 2) = 0u;
                *reinterpret_cast<uint32_t*>(smem + SP_B + rhi * LDPB + c * 2) = 0u;
            }
        }
    }
    __syncthreads();

    // =============== Phase 2c: O = P @ V ===============
    const int n03 = wn * 16;
    float acc3[2][2][4];
#pragma unroll
    for (int i = 0; i < 2; i++)
#pragma unroll
        for (int j = 0; j < 2; j++)
#pragma unroll
            for (int r = 0; r < 4; r++) acc3[i][j][r] = 0.f;

    const uint32_t prow = sbase + SP_B + (m0 + (lane & 15)) * LDPB + (lane >> 4) * 16;
#pragma unroll
    for (int kt = 0; kt < 8; kt++) {
        uint32_t a[2][4], bv[4];
#pragma unroll
        for (int mt = 0; mt < 2; mt++) LDSM_X4(a[mt], prow + mt * 16 * LDPB + kt * 32);
        uint32_t vaddr = sbase + SV_B
                       + (kt * 16 + ((lane >> 3) & 1) * 8 + (lane & 7)) * LDA
                       + (lane >> 4) * 16 + n03 * 2;
        LDSM_X4T(bv, vaddr);
#pragma unroll
        for (int mt = 0; mt < 2; mt++) {
            MMA16816(acc3[mt][0], a[mt], bv[0], bv[1]);
            MMA16816(acc3[mt][1], a[mt], bv[2], bv[3]);
        }
    }

    // output: fp32 float2 stores
    float* ob = out + b * (size_t)(T_SEQ * H_DIM);
#pragma unroll
    for (int mt = 0; mt < 2; mt++) {
        int rlo = m0 + mt * 16 + g, rhi = rlo + 8;
#pragma unroll
        for (int nt = 0; nt < 2; nt++) {
            int c = n03 + nt * 8 + t * 2;
            *reinterpret_cast<float2*>(ob + rlo * H_DIM + c) =
                make_float2(acc3[mt][nt][0], acc3[mt][nt][1]);
            *reinterpret_cast<float2*>(ob + rhi * H_DIM + c) =
                make_float2(acc3[mt][nt][2], acc3[mt][nt][3]);
        }
    }
}

extern "C" void kernel_launch(void* const* d_in, const int* in_sizes, int n_in,
                              void* d_out, int out_size) {
    const float* x  = (const float*)d_in[0];
    const float* Wq = (const float*)d_in[1];
    const float* Wk = (const float*)d_in[2];
    const float* Wv = (const float*)d_in[3];
    float* out = (float*)d_out;

    int B = in_sizes[0] / (T_SEQ * E_DIM);   // 4096

    cudaFuncSetAttribute(attn_fp16_kernel,
                         cudaFuncAttributeMaxDynamicSharedMemorySize,
                         (int)SMEM_BYTES);

    prep_w_kernel<<<12, 256>>>(Wq, Wk, Wv);
    attn_fp16_kernel<<<B, 512, SMEM_BYTES>>>(x, out);
}